// round 14
// baseline (speedup 1.0000x reference)
#include <cuda_runtime.h>

#define NV 96
#define NNE 9216
#define LAT 256
#define OUTD 4656
#define ITERS 50
#define FULLW 0xffffffffu
#define KINIT 0xFFFFFFFEu
#define NC 48
#define TPB 192

__device__ float g_p_mu[16][LAT];
__device__ float g_p_ls[16][LAT];
__device__ float g_p_y[16][LAT];
__device__ float g_out[OUTD];
__device__ float g_xf[NNE];
__device__ float g_M[2][NNE];
__device__ int   g_scale[64];
__device__ unsigned g_arr[NC];     // monotonic barrier flags

// ---------------- MLP ----------------
__global__ void k_gemv1(const float* __restrict__ h, const float* __restrict__ Wmu,
                        const float* __restrict__ Wls) {
    __shared__ float sh[576];
    int c = blockIdx.x, mat = blockIdx.y, o = threadIdx.x;
    int k0 = c * 576;
    for (int kk = o; kk < 576; kk += 256) sh[kk] = h[k0 + kk];
    __syncthreads();
    const float* Wp = (mat ? Wls : Wmu) + (size_t)k0 * LAT + o;
    float acc = 0.f;
#pragma unroll 4
    for (int kk = 0; kk < 576; kk++) acc += sh[kk] * Wp[(size_t)kk * LAT];
    if (mat) g_p_ls[c][o] = acc; else g_p_mu[c][o] = acc;
}

__global__ void k_gemv2(const float* __restrict__ h, const float* __restrict__ Wd1,
                        const float* __restrict__ bmu) {
    __shared__ float sh[592];
    int c = blockIdx.x, o = threadIdx.x;
    int k0 = c * 592;
    for (int kk = o; kk < 592; kk += 256) {
        int k = k0 + kk;
        float v;
        if (k < NNE) v = h[k];
        else {
            int oo = k - NNE;
            v = bmu[oo];
#pragma unroll
            for (int cc = 0; cc < 16; cc++) v += g_p_mu[cc][oo];
        }
        sh[kk] = v;
    }
    __syncthreads();
    const float* Wp = Wd1 + (size_t)k0 * LAT + o;
    float acc = 0.f;
#pragma unroll 4
    for (int kk = 0; kk < 592; kk++) acc += sh[kk] * Wp[(size_t)kk * LAT];
    g_p_y[c][o] = acc;
}

__global__ void k_out(const float* __restrict__ Wd2, const float* __restrict__ bd2,
                      const float* __restrict__ bd1) {
    __shared__ float ys[LAT];
    int t = threadIdx.x;
    {
        float s = bd1[t];
#pragma unroll
        for (int c = 0; c < 16; c++) s += g_p_y[c][t];
        ys[t] = fmaxf(s, 0.f);
    }
    __syncthreads();
    int o = blockIdx.x * 256 + t;
    if (o < OUTD) {
        float acc = bd2[o];
#pragma unroll 4
        for (int k = 0; k < LAT; k++) acc += ys[k] * Wd2[(size_t)k * OUTD + o];
        g_out[o] = 1.f / (1.f + expf(-acc));
    }
}

// ---------------- helpers ----------------
__device__ __forceinline__ int triidx(int a, int b) {
    return a * NV - (a * (a - 1)) / 2 + (b - a);
}
__device__ __forceinline__ float rec_of(int i, int j) {
    int a = min(i, j), b = max(i, j);
    return g_out[triidx(a, b)];
}
__device__ __forceinline__ unsigned fmap(float x) {
    unsigned b = __float_as_uint(x);
    return b ^ ((unsigned)(((int)b) >> 31) | 0x80000000u);
}
__device__ __forceinline__ float funmap(unsigned k) {
    return __uint_as_float((k & 0x80000000u) ? (k ^ 0x80000000u) : ~k);
}

// ---------------- mega persistent kernel ----------------
__global__ void __launch_bounds__(TPB, 1) k_mega(const float* __restrict__ adj,
                                                 const float* __restrict__ bmu,
                                                 const float* __restrict__ bls,
                                                 float* __restrict__ out) {
    extern __shared__ float dyn[];
    float* Bs = dyn;               // 96*97
    float* Ms = dyn + NV * 97;     // 9216 (xf in hung)
    __shared__ float sd[NV], snf[NV], sdr[NV], snfr[NV];
    __shared__ float As2[2][NV], Ds2[2][NV], xr2[2][NV];
    __shared__ float red[6], redk[6];
    __shared__ float u_[97], vcol[97], rmin_[97];
    __shared__ int p_[97], way_[97], rowof_[97], rarg_[97], fl[NV], fl2[NV];
    __shared__ int st_row[100], st_col[100];
    __shared__ int indsh[NV];
    __shared__ int sn0;
    __shared__ unsigned sbase;

    int tid = threadIdx.x, bid = blockIdx.x;
    int hf = tid / NV;
    int col = tid - hf * NV;
    int grow = bid * 2 + hf;
    if (tid == 0) sbase = *(volatile unsigned*)&g_arr[bid];

    // ---- setup ----
    if (tid < NV) {
        float drt = 0.f, nfrt = 0.f;
        for (int i = 0; i < NV; i++) {
            float r = rec_of(i, tid);
            nfrt += r;
            if (i == tid) drt = r;
        }
        sdr[tid] = drt;
        snfr[tid] = nfrt;
        float nft = 0.f;
        const float* arow = adj + tid * NV;
        for (int j = 0; j < NV; j++) nft += arow[j];
        sd[tid] = arow[tid];
        snf[tid] = nft;
    }
    __syncthreads();
    if (tid < NV) {
        float drt = sdr[tid];
        for (int i = 0; i < NV; i++)
            Bs[i * 97 + tid] = (i == tid) ? 0.f : rec_of(i, tid) * sdr[i] * drt;
    }
    As2[hf][col] = (grow == col) ? 0.f : adj[grow * NV + col] * sd[grow] * sd[col];
    Ds2[hf][col] = sd[grow] * sdr[col] / (fabsf(snf[grow] - snfr[col]) + 1.f);
    xr2[hf][col] = 1.f / 96.f;
    if (tid == 0) g_scale[0] = __float_as_int(1.0f);
    if (tid >= 1 && tid < 64) g_scale[tid] = 0;
    __syncthreads();
    unsigned base = sbase;

    // ---- MPM (bit-identical to R9/R13) ----
    for (int it = 0; it < ITERS; it++) {
        int mb = it & 1;
        float xv = xr2[hf][col];
        float m0 = 0.f, m1 = 0.f, m2 = 0.f, m3 = 0.f;
#pragma unroll
        for (int b = 0; b < NV; b += 4) {
            m0 = fmaxf(m0, xr2[hf][b] * Bs[b * 97 + col]);
            m1 = fmaxf(m1, xr2[hf][b + 1] * Bs[(b + 1) * 97 + col]);
            m2 = fmaxf(m2, xr2[hf][b + 2] * Bs[(b + 2) * 97 + col]);
            m3 = fmaxf(m3, xr2[hf][b + 3] * Bs[(b + 3) * 97 + col]);
        }
        __stcg(&g_M[mb][grow * NV + col], fmaxf(fmaxf(m0, m1), fmaxf(m2, m3)));
        __syncthreads();
        unsigned tgt = base + (unsigned)(it + 1);
        if (tid == 0) { __threadfence(); *(volatile unsigned*)&g_arr[bid] = tgt; }
        {
            volatile unsigned* f = (volatile unsigned*)&g_arr[tid % NC];
            while (*f < tgt) { }
        }
        __threadfence();
        __syncthreads();
        {
            const float4* src = (const float4*)&g_M[mb][0];
            float4* dst = (float4*)Ms;
            for (int i4 = tid; i4 < NNE / 4; i4 += TPB) dst[i4] = __ldcg(src + i4);
        }
        __syncthreads();
        float sv = __int_as_float(*(volatile int*)&g_scale[it]);
        float inv = (sv > 0.f) ? 1.f / sv : 1.f;
        float a0 = xv * Ds2[hf][col], a1 = 0.f, a2 = 0.f, a3 = 0.f;
#pragma unroll
        for (int j = 0; j < NV; j += 4) {
            a0 += As2[hf][j] * Ms[j * NV + col];
            a1 += As2[hf][j + 1] * Ms[(j + 1) * NV + col];
            a2 += As2[hf][j + 2] * Ms[(j + 2) * NV + col];
            a3 += As2[hf][j + 3] * Ms[(j + 3) * NV + col];
        }
        float acc = ((a0 + a1) + (a2 + a3)) * inv;
        xr2[hf][col] = acc;
        float bm = acc;
        for (int off = 16; off; off >>= 1) bm = fmaxf(bm, __shfl_down_sync(FULLW, bm, off));
        if ((tid & 31) == 0) red[tid >> 5] = bm;
        __syncthreads();
        if (tid == 0) {
            float g = fmaxf(fmaxf(fmaxf(red[0], red[1]), fmaxf(red[2], red[3])),
                            fmaxf(red[4], red[5]));
            atomicMax(&g_scale[it + 1], __float_as_int(g));
        }
    }
    __syncthreads();
    g_xf[grow * NV + col] = xr2[hf][col];
    {
        __syncthreads();
        unsigned tgt = base + (unsigned)(ITERS + 1);
        if (tid == 0) { __threadfence(); *(volatile unsigned*)&g_arr[bid] = tgt; }
        volatile unsigned* f = (volatile unsigned*)&g_arr[tid % NC];
        while (*f < tgt) { }
        __threadfence();
        __syncthreads();
    }
    if (bid != 0) return;

    // ======== CTA 0: Hungarian fp32 ========
    float* xf = Ms;
    for (int idx = tid; idx < NNE; idx += TPB) xf[idx] = __ldcg(&g_xf[idx]);
    if (tid < 97) { u_[tid] = 0.f; p_[tid] = 0; way_[tid] = 0; rowof_[tid] = 0; }
    __syncthreads();
    // Phase A: column reduction
    if (tid < NV) {
        float best = 1e30f; int bi = 1;
        for (int i2 = 0; i2 < NV; i2++) {
            float cv = -xf[i2 * NV + tid];
            if (cv < best) { best = cv; bi = i2 + 1; }
        }
        vcol[tid + 1] = best;
        rowof_[tid + 1] = bi;
    }
    __syncthreads();
    // Phase B: greedy column assignment
    if (tid == 0) {
        int cnt = 0;
        for (int j = 1; j <= NV; j++) {
            int i = rowof_[j];
            if (way_[i] == 0) { way_[i] = 1; p_[j] = i; }
        }
        for (int i = 1; i <= NV; i++) if (way_[i] == 0) fl[cnt++] = i;
        for (int i = 0; i <= NV; i++) way_[i] = 0;
        sn0 = cnt;
    }
    __syncthreads();
    // Phase B1: row reduction for free rows (exact, dual-feasible)
    if (tid < NV) {
        int i = tid + 1;
        float best = 1e30f; int bj = 1;
        const float* crow = &xf[tid * NV];
        for (int j = 1; j <= NV; j++) {
            float cv = -crow[j - 1] - vcol[j];
            if (cv < best) { best = cv; bj = j; }
        }
        rmin_[i] = best;
        rarg_[i] = bj;
    }
    __syncthreads();
    if (tid == 0) {
        int cnt = 0;
        int n0 = sn0;
        for (int k = 0; k < n0; k++) {
            int i = fl[k];
            u_[i] = rmin_[i];
            int j = rarg_[i];
            if (p_[j] == 0) p_[j] = i;
            else fl2[cnt++] = i;
        }
        for (int k = 0; k < cnt; k++) fl[k] = fl2[k];
        sn0 = cnt;
    }
    __syncthreads();
    // Phase B2: Kuhn augmentation on the ZERO-reduced-cost graph (warp 0).
    // Only tight edges ((-c - v) == u bitwise) are traversed; p_ written only on
    // success, so a failed search leaves state untouched -> row falls to Dijkstra.
    if (tid < 32) {
        int lane = tid;
        const int J0 = 1 + lane, J1 = 33 + lane, J2 = 65 + lane;
        float vst0 = vcol[J0], vst1 = vcol[J1], vst2 = vcol[J2];
        int nf = sn0;
        for (int idx = 0; idx < nf; idx++) {
            int i = fl[idx];
            bool v0 = false, v1 = false, v2 = false;
            int depth = 0;
            int r = i;
            bool ok = false;
            for (int it2 = 0; it2 < 256; it2++) {
                float ur = u_[r];
                const float* crow = &xf[(r - 1) * NV];
                int cand = 255;
                if (!v2 && ((-crow[J2 - 1] - vst2) == ur)) cand = J2;
                if (!v1 && ((-crow[J1 - 1] - vst1) == ur)) cand = J1;
                if (!v0 && ((-crow[J0 - 1] - vst0) == ur)) cand = J0;
                int jc = __reduce_min_sync(FULLW, cand);
                if (jc == 255) {
                    if (depth == 0) break;   // fail
                    depth--;
                    r = st_row[depth];
                    continue;
                }
                if (((jc - 1) & 31) == lane) {
                    int sl = (jc - 1) >> 5;
                    if (sl == 0) v0 = true; else if (sl == 1) v1 = true; else v2 = true;
                }
                int pj = p_[jc];
                if (lane == 0) { st_row[depth] = r; st_col[depth] = jc; }
                __syncwarp();
                if (pj == 0) { ok = true; break; }
                depth++;
                r = pj;
            }
            if (ok && lane == 0) {
                for (int k = 0; k <= depth; k++) p_[st_col[k]] = st_row[k];
            }
            __syncwarp();
        }
    }
    __syncthreads();
    // rebuild free list from p_ (deterministic)
    if (tid == 0) {
        for (int r = 0; r <= NV; r++) way_[r] = 0;
        for (int j = 1; j <= NV; j++) { int r = p_[j]; if (r) way_[r] = 1; }
        int cnt = 0;
        for (int r = 1; r <= NV; r++) if (!way_[r]) fl[cnt++] = r;
        sn0 = cnt;
        for (int r = 0; r <= NV; r++) way_[r] = 0;
    }
    __syncthreads();
    // Phase C: branchless absolute-dist Dijkstra (warp 0) — unchanged from R13
    if (tid < 32) {
        int lane = tid;
        const int J0 = 1 + lane, J1 = 33 + lane, J2 = 65 + lane;
        float vst0 = vcol[J0], vst1 = vcol[J1], vst2 = vcol[J2];
        int pr0 = p_[J0], pr1 = p_[J1], pr2 = p_[J2];
        float uo0 = pr0 ? u_[pr0] : 0.f;
        float uo1 = pr1 ? u_[pr1] : 0.f;
        float uo2 = pr2 ? u_[pr2] : 0.f;
        int nf = sn0;
        for (int idx = 0; idx < nf; idx++) {
            int i = fl[idx];
            if (lane == 0) p_[0] = i;
            unsigned k0 = KINIT, k1 = KINIT, k2 = KINIT;
            float su0 = 0.f, su1 = 0.f, su2 = 0.f;
            float S = 0.f;
            float ui0 = u_[i];
            int i0 = i;
            int j0 = 0;
            __syncwarp();
            while (true) {
                bool h0 = (j0 == J0), h1 = (j0 == J1), h2 = (j0 == J2);
                su0 = h0 ? S : su0; su1 = h1 ? S : su1; su2 = h2 ? S : su2;
                k0 = h0 ? ~0u : k0; k1 = h1 ? ~0u : k1; k2 = h2 ? ~0u : k2;
                bool s0 = (k0 == ~0u), s1 = (k1 == ~0u), s2 = (k2 == ~0u);
                const float* crow = &xf[(i0 - 1) * NV];
                float c0 = (-crow[J0 - 1] - ui0 - vst0) + S;
                float c1 = (-crow[J1 - 1] - ui0 - vst1) + S;
                float c2 = (-crow[J2 - 1] - ui0 - vst2) + S;
                unsigned kc0 = fmap(c0), kc1 = fmap(c1), kc2 = fmap(c2);
                bool up0 = !s0 && (kc0 < k0);
                bool up1 = !s1 && (kc1 < k1);
                bool up2 = !s2 && (kc2 < k2);
                way_[up0 ? J0 : 0] = j0;
                way_[up1 ? J1 : 0] = j0;
                way_[up2 ? J2 : 0] = j0;
                k0 = up0 ? kc0 : k0;
                k1 = up1 ? kc1 : k1;
                k2 = up2 ? kc2 : k2;
                unsigned lb = min(k0, min(k1, k2));
                unsigned g = __reduce_min_sync(FULLW, lb);
                unsigned bb = __ballot_sync(FULLW, lb == g);
                int owner = __ffs(bb) - 1;
                int pk; float ul;
                if (k0 == g)      { pk = J0 | (pr0 << 8); ul = uo0; }
                else if (k1 == g) { pk = J1 | (pr1 << 8); ul = uo1; }
                else              { pk = J2 | (pr2 << 8); ul = uo2; }
                pk = __shfl_sync(FULLW, pk, owner);
                ui0 = __shfl_sync(FULLW, ul, owner);
                S = funmap(g);
                j0 = pk & 0xff;
                int pj = pk >> 8;
                if (pj == 0) break;
                i0 = pj;
            }
            float Sf = S;
            if (k0 == ~0u) { float d = Sf - su0; vst0 -= d; if (pr0) u_[pr0] += d; }
            if (k1 == ~0u) { float d = Sf - su1; vst1 -= d; if (pr1) u_[pr1] += d; }
            if (k2 == ~0u) { float d = Sf - su2; vst2 -= d; if (pr2) u_[pr2] += d; }
            __syncwarp();
            if (lane == 0) {
                u_[i] += Sf;
                int jj = j0;
                while (jj) { int jn = way_[jj]; p_[jj] = p_[jn]; jj = jn; }
            }
            __syncwarp();
            pr0 = p_[J0]; pr1 = p_[J1]; pr2 = p_[J2];
            uo0 = pr0 ? u_[pr0] : 0.f;
            uo1 = pr1 ? u_[pr1] : 0.f;
            uo2 = pr2 ? u_[pr2] : 0.f;
            __syncwarp();
        }
    }
    __syncthreads();
    if (tid < NV) indsh[tid] = max(p_[tid + 1] - 1, 0);
    __syncthreads();

    // ---- final loss ----
    float s = 0.f;
    for (int idx = tid; idx < OUTD; idx += TPB) {
        int i = (int)((193.0 - sqrt(193.0 * 193.0 - 8.0 * (double)idx)) * 0.5);
        if (i < 0) i = 0;
        if (i > 95) i = 95;
        while (i > 0 && (i * (193 - i)) / 2 > idx) i--;
        while (i < 95 && ((i + 1) * (192 - i)) / 2 <= idx) i++;
        int j = i + idx - (i * (193 - i)) / 2;
        float a = adj[indsh[i] * NV + indsh[j]];
        float t = g_out[idx];
        s += fmaxf(a, 0.f) - a * t + log1pf(expf(-fabsf(a)));
    }
    float w = 0.f;
    for (int o = tid; o < LAT; o += TPB) {
        float smu = bmu[o], sls = bls[o];
#pragma unroll
        for (int c = 0; c < 16; c++) { smu += g_p_mu[c][o]; sls += g_p_ls[c][o]; }
        w += 1.f + sls - smu * smu - expf(sls);
    }
    for (int off = 16; off; off >>= 1) {
        s += __shfl_down_sync(FULLW, s, off);
        w += __shfl_down_sync(FULLW, w, off);
    }
    if ((tid & 31) == 0) { red[tid >> 5] = s; redk[tid >> 5] = w; }
    __syncthreads();
    if (tid == 0) {
        float S = ((red[0] + red[1]) + (red[2] + red[3])) + (red[4] + red[5]);
        float W = ((redk[0] + redk[1]) + (redk[2] + redk[3])) + (redk[4] + redk[5]);
        out[0] = S / (float)OUTD + (-0.5f * W / (float)NNE);
    }
}

extern "C" void kernel_launch(void* const* d_in, const int* in_sizes, int n_in,
                              void* d_out, int out_size) {
    const float* h   = (const float*)d_in[0];
    const float* adj = (const float*)d_in[1];
    const float* Wmu = (const float*)d_in[2];
    const float* bmu = (const float*)d_in[3];
    const float* Wls = (const float*)d_in[4];
    const float* bls = (const float*)d_in[5];
    const float* Wd1 = (const float*)d_in[6];
    const float* bd1 = (const float*)d_in[7];
    const float* Wd2 = (const float*)d_in[8];
    const float* bd2 = (const float*)d_in[9];
    float* out = (float*)d_out;

    static int smem_set = 0;
    if (!smem_set) {
        cudaFuncSetAttribute(k_mega, cudaFuncAttributeMaxDynamicSharedMemorySize,
                             (NV * 97 + NNE) * 4);
        smem_set = 1;
    }

    dim3 g1(16, 2);
    k_gemv1<<<g1, 256>>>(h, Wmu, Wls);
    k_gemv2<<<16, 256>>>(h, Wd1, bmu);
    k_out<<<19, 256>>>(Wd2, bd2, bd1);
    k_mega<<<NC, TPB, (NV * 97 + NNE) * 4>>>(adj, bmu, bls, out);
}

// round 15
// speedup vs baseline: 1.0455x; 1.0455x over previous
#include <cuda_runtime.h>

#define NV 96
#define NNE 9216
#define LAT 256
#define OUTD 4656
#define ITERS 50
#define FULLW 0xffffffffu
#define KINIT 0xFFFFFFFEu
#define NC 48
#define TPB 192

__device__ float g_p_mu[16][LAT];
__device__ float g_p_ls[16][LAT];
__device__ float g_p_y[16][LAT];
__device__ float g_out[OUTD];
__device__ float g_xf[NNE];
__device__ float g_M[2][NNE];
__device__ int   g_scale[64];
__device__ unsigned g_arr[NC];     // monotonic barrier flags

// ---------------- MLP ----------------
__global__ void k_gemv1(const float* __restrict__ h, const float* __restrict__ Wmu,
                        const float* __restrict__ Wls) {
    __shared__ float sh[576];
    int c = blockIdx.x, mat = blockIdx.y, o = threadIdx.x;
    int k0 = c * 576;
    for (int kk = o; kk < 576; kk += 256) sh[kk] = h[k0 + kk];
    __syncthreads();
    const float* Wp = (mat ? Wls : Wmu) + (size_t)k0 * LAT + o;
    float acc = 0.f;
#pragma unroll 4
    for (int kk = 0; kk < 576; kk++) acc += sh[kk] * Wp[(size_t)kk * LAT];
    if (mat) g_p_ls[c][o] = acc; else g_p_mu[c][o] = acc;
}

__global__ void k_gemv2(const float* __restrict__ h, const float* __restrict__ Wd1,
                        const float* __restrict__ bmu) {
    __shared__ float sh[592];
    int c = blockIdx.x, o = threadIdx.x;
    int k0 = c * 592;
    for (int kk = o; kk < 592; kk += 256) {
        int k = k0 + kk;
        float v;
        if (k < NNE) v = h[k];
        else {
            int oo = k - NNE;
            v = bmu[oo];
#pragma unroll
            for (int cc = 0; cc < 16; cc++) v += g_p_mu[cc][oo];
        }
        sh[kk] = v;
    }
    __syncthreads();
    const float* Wp = Wd1 + (size_t)k0 * LAT + o;
    float acc = 0.f;
#pragma unroll 4
    for (int kk = 0; kk < 592; kk++) acc += sh[kk] * Wp[(size_t)kk * LAT];
    g_p_y[c][o] = acc;
}

__global__ void k_out(const float* __restrict__ Wd2, const float* __restrict__ bd2,
                      const float* __restrict__ bd1) {
    __shared__ float ys[LAT];
    int t = threadIdx.x;
    {
        float s = bd1[t];
#pragma unroll
        for (int c = 0; c < 16; c++) s += g_p_y[c][t];
        ys[t] = fmaxf(s, 0.f);
    }
    __syncthreads();
    int o = blockIdx.x * 256 + t;
    if (o < OUTD) {
        float acc = bd2[o];
#pragma unroll 4
        for (int k = 0; k < LAT; k++) acc += ys[k] * Wd2[(size_t)k * OUTD + o];
        g_out[o] = 1.f / (1.f + expf(-acc));
    }
}

// ---------------- helpers ----------------
__device__ __forceinline__ int triidx(int a, int b) {
    return a * NV - (a * (a - 1)) / 2 + (b - a);
}
__device__ __forceinline__ float rec_of(int i, int j) {
    int a = min(i, j), b = max(i, j);
    return g_out[triidx(a, b)];
}
__device__ __forceinline__ unsigned fmap(float x) {
    unsigned b = __float_as_uint(x);
    return b ^ ((unsigned)(((int)b) >> 31) | 0x80000000u);
}
__device__ __forceinline__ float funmap(unsigned k) {
    return __uint_as_float((k & 0x80000000u) ? (k ^ 0x80000000u) : ~k);
}

// ---------------- MPM persistent kernel (48 CTAs x 192 thr, bit-identical to R13) ----------------
__global__ void __launch_bounds__(TPB, 1) k_mpm(const float* __restrict__ adj) {
    extern __shared__ float dyn[];
    float* Bs = dyn;               // 96*97
    float* Ms = dyn + NV * 97;     // 9216
    __shared__ float sd[NV], snf[NV], sdr[NV], snfr[NV];
    __shared__ float As2[2][NV], Ds2[2][NV], xr2[2][NV];
    __shared__ float red[6];
    __shared__ unsigned sbase;

    int tid = threadIdx.x, bid = blockIdx.x;
    int hf = tid / NV;
    int col = tid - hf * NV;
    int grow = bid * 2 + hf;
    if (tid == 0) sbase = *(volatile unsigned*)&g_arr[bid];

    // ---- setup ----
    if (tid < NV) {
        float drt = 0.f, nfrt = 0.f;
        for (int i = 0; i < NV; i++) {
            float r = rec_of(i, tid);
            nfrt += r;
            if (i == tid) drt = r;
        }
        sdr[tid] = drt;
        snfr[tid] = nfrt;
        float nft = 0.f;
        const float* arow = adj + tid * NV;
        for (int j = 0; j < NV; j++) nft += arow[j];
        sd[tid] = arow[tid];
        snf[tid] = nft;
    }
    __syncthreads();
    if (tid < NV) {
        float drt = sdr[tid];
        for (int i = 0; i < NV; i++)
            Bs[i * 97 + tid] = (i == tid) ? 0.f : rec_of(i, tid) * sdr[i] * drt;
    }
    As2[hf][col] = (grow == col) ? 0.f : adj[grow * NV + col] * sd[grow] * sd[col];
    Ds2[hf][col] = sd[grow] * sdr[col] / (fabsf(snf[grow] - snfr[col]) + 1.f);
    xr2[hf][col] = 1.f / 96.f;
    if (tid == 0) g_scale[0] = __float_as_int(1.0f);
    if (tid >= 1 && tid < 64) g_scale[tid] = 0;
    __syncthreads();
    unsigned base = sbase;

    for (int it = 0; it < ITERS; it++) {
        int mb = it & 1;
        float xv = xr2[hf][col];
        float m0 = 0.f, m1 = 0.f, m2 = 0.f, m3 = 0.f;
#pragma unroll
        for (int b = 0; b < NV; b += 4) {
            m0 = fmaxf(m0, xr2[hf][b] * Bs[b * 97 + col]);
            m1 = fmaxf(m1, xr2[hf][b + 1] * Bs[(b + 1) * 97 + col]);
            m2 = fmaxf(m2, xr2[hf][b + 2] * Bs[(b + 2) * 97 + col]);
            m3 = fmaxf(m3, xr2[hf][b + 3] * Bs[(b + 3) * 97 + col]);
        }
        __stcg(&g_M[mb][grow * NV + col], fmaxf(fmaxf(m0, m1), fmaxf(m2, m3)));
        __syncthreads();
        unsigned tgt = base + (unsigned)(it + 1);
        if (tid == 0) { __threadfence(); *(volatile unsigned*)&g_arr[bid] = tgt; }
        {
            volatile unsigned* f = (volatile unsigned*)&g_arr[tid % NC];
            while (*f < tgt) { }
        }
        __threadfence();
        __syncthreads();
        {
            const float4* src = (const float4*)&g_M[mb][0];
            float4* dst = (float4*)Ms;
            for (int i4 = tid; i4 < NNE / 4; i4 += TPB) dst[i4] = __ldcg(src + i4);
        }
        __syncthreads();
        float sv = __int_as_float(*(volatile int*)&g_scale[it]);
        float inv = (sv > 0.f) ? 1.f / sv : 1.f;
        float a0 = xv * Ds2[hf][col], a1 = 0.f, a2 = 0.f, a3 = 0.f;
#pragma unroll
        for (int j = 0; j < NV; j += 4) {
            a0 += As2[hf][j] * Ms[j * NV + col];
            a1 += As2[hf][j + 1] * Ms[(j + 1) * NV + col];
            a2 += As2[hf][j + 2] * Ms[(j + 2) * NV + col];
            a3 += As2[hf][j + 3] * Ms[(j + 3) * NV + col];
        }
        float acc = ((a0 + a1) + (a2 + a3)) * inv;
        xr2[hf][col] = acc;
        float bm = acc;
        for (int off = 16; off; off >>= 1) bm = fmaxf(bm, __shfl_down_sync(FULLW, bm, off));
        if ((tid & 31) == 0) red[tid >> 5] = bm;
        __syncthreads();
        if (tid == 0) {
            float g = fmaxf(fmaxf(fmaxf(red[0], red[1]), fmaxf(red[2], red[3])),
                            fmaxf(red[4], red[5]));
            atomicMax(&g_scale[it + 1], __float_as_int(g));
        }
    }
    __syncthreads();
    g_xf[grow * NV + col] = xr2[hf][col];
    // kernel boundary provides the final sync before k_hung
}

// ---------------- Hungarian + loss (single CTA, byte-identical logic to R13) ----------------
__global__ void __launch_bounds__(TPB, 1) k_hung(const float* __restrict__ adj,
                                                 const float* __restrict__ bmu,
                                                 const float* __restrict__ bls,
                                                 float* __restrict__ out) {
    extern __shared__ float dyn[];
    float* xf = dyn;               // 9216
    __shared__ float red[6], redk[6];
    __shared__ float u_[97], vcol[97], rmin_[97];
    __shared__ int p_[97], way_[97], rowof_[97], rarg_[97], fl[NV], fl2[NV];
    __shared__ int indsh[NV];
    __shared__ int sn0;
    int tid = threadIdx.x;

    for (int idx = tid; idx < NNE; idx += TPB) xf[idx] = __ldcg(&g_xf[idx]);
    if (tid < 97) { u_[tid] = 0.f; p_[tid] = 0; way_[tid] = 0; rowof_[tid] = 0; }
    __syncthreads();
    // Phase A: column reduction
    if (tid < NV) {
        float best = 1e30f; int bi = 1;
        for (int i2 = 0; i2 < NV; i2++) {
            float cv = -xf[i2 * NV + tid];
            if (cv < best) { best = cv; bi = i2 + 1; }
        }
        vcol[tid + 1] = best;
        rowof_[tid + 1] = bi;
    }
    __syncthreads();
    // Phase B: greedy column assignment
    if (tid == 0) {
        int cnt = 0;
        for (int j = 1; j <= NV; j++) {
            int i = rowof_[j];
            if (way_[i] == 0) { way_[i] = 1; p_[j] = i; }
        }
        for (int i = 1; i <= NV; i++) if (way_[i] == 0) fl[cnt++] = i;
        for (int i = 0; i <= NV; i++) way_[i] = 0;
        sn0 = cnt;
    }
    __syncthreads();
    // Phase B1: row reduction for free rows
    if (tid < NV) {
        int i = tid + 1;
        float best = 1e30f; int bj = 1;
        const float* crow = &xf[tid * NV];
        for (int j = 1; j <= NV; j++) {
            float cv = -crow[j - 1] - vcol[j];
            if (cv < best) { best = cv; bj = j; }
        }
        rmin_[i] = best;
        rarg_[i] = bj;
    }
    __syncthreads();
    if (tid == 0) {
        int cnt = 0;
        int n0 = sn0;
        for (int k = 0; k < n0; k++) {
            int i = fl[k];
            u_[i] = rmin_[i];
            int j = rarg_[i];
            if (p_[j] == 0) p_[j] = i;
            else fl2[cnt++] = i;
        }
        for (int k = 0; k < cnt; k++) fl[k] = fl2[k];
        sn0 = cnt;
    }
    __syncthreads();
    // Phase C: branchless absolute-dist Dijkstra (warp 0)
    if (tid < 32) {
        int lane = tid;
        const int J0 = 1 + lane, J1 = 33 + lane, J2 = 65 + lane;
        float vst0 = vcol[J0], vst1 = vcol[J1], vst2 = vcol[J2];
        int pr0 = p_[J0], pr1 = p_[J1], pr2 = p_[J2];
        float uo0 = pr0 ? u_[pr0] : 0.f;
        float uo1 = pr1 ? u_[pr1] : 0.f;
        float uo2 = pr2 ? u_[pr2] : 0.f;
        int nf = sn0;
        for (int idx = 0; idx < nf; idx++) {
            int i = fl[idx];
            if (lane == 0) p_[0] = i;
            unsigned k0 = KINIT, k1 = KINIT, k2 = KINIT;
            float su0 = 0.f, su1 = 0.f, su2 = 0.f;
            float S = 0.f;
            float ui0 = u_[i];
            int i0 = i;
            int j0 = 0;
            __syncwarp();
            while (true) {
                bool h0 = (j0 == J0), h1 = (j0 == J1), h2 = (j0 == J2);
                su0 = h0 ? S : su0; su1 = h1 ? S : su1; su2 = h2 ? S : su2;
                k0 = h0 ? ~0u : k0; k1 = h1 ? ~0u : k1; k2 = h2 ? ~0u : k2;
                bool s0 = (k0 == ~0u), s1 = (k1 == ~0u), s2 = (k2 == ~0u);
                const float* crow = &xf[(i0 - 1) * NV];
                float c0 = (-crow[J0 - 1] - ui0 - vst0) + S;
                float c1 = (-crow[J1 - 1] - ui0 - vst1) + S;
                float c2 = (-crow[J2 - 1] - ui0 - vst2) + S;
                unsigned kc0 = fmap(c0), kc1 = fmap(c1), kc2 = fmap(c2);
                bool up0 = !s0 && (kc0 < k0);
                bool up1 = !s1 && (kc1 < k1);
                bool up2 = !s2 && (kc2 < k2);
                way_[up0 ? J0 : 0] = j0;       // way_[0] = trash, never read
                way_[up1 ? J1 : 0] = j0;
                way_[up2 ? J2 : 0] = j0;
                k0 = up0 ? kc0 : k0;
                k1 = up1 ? kc1 : k1;
                k2 = up2 ? kc2 : k2;
                unsigned lb = min(k0, min(k1, k2));
                unsigned g = __reduce_min_sync(FULLW, lb);
                unsigned bb = __ballot_sync(FULLW, lb == g);
                int owner = __ffs(bb) - 1;
                int pk; float ul;
                if (k0 == g)      { pk = J0 | (pr0 << 8); ul = uo0; }
                else if (k1 == g) { pk = J1 | (pr1 << 8); ul = uo1; }
                else              { pk = J2 | (pr2 << 8); ul = uo2; }
                pk = __shfl_sync(FULLW, pk, owner);
                ui0 = __shfl_sync(FULLW, ul, owner);
                S = funmap(g);
                j0 = pk & 0xff;
                int pj = pk >> 8;
                if (pj == 0) break;
                i0 = pj;
            }
            float Sf = S;
            if (k0 == ~0u) { float d = Sf - su0; vst0 -= d; if (pr0) u_[pr0] += d; }
            if (k1 == ~0u) { float d = Sf - su1; vst1 -= d; if (pr1) u_[pr1] += d; }
            if (k2 == ~0u) { float d = Sf - su2; vst2 -= d; if (pr2) u_[pr2] += d; }
            __syncwarp();
            if (lane == 0) {
                u_[i] += Sf;
                int jj = j0;
                while (jj) { int jn = way_[jj]; p_[jj] = p_[jn]; jj = jn; }
            }
            __syncwarp();
            pr0 = p_[J0]; pr1 = p_[J1]; pr2 = p_[J2];
            uo0 = pr0 ? u_[pr0] : 0.f;
            uo1 = pr1 ? u_[pr1] : 0.f;
            uo2 = pr2 ? u_[pr2] : 0.f;
            __syncwarp();
        }
    }
    __syncthreads();
    if (tid < NV) indsh[tid] = max(p_[tid + 1] - 1, 0);
    __syncthreads();

    // ---- final loss ----
    float s = 0.f;
    for (int idx = tid; idx < OUTD; idx += TPB) {
        int i = (int)((193.0 - sqrt(193.0 * 193.0 - 8.0 * (double)idx)) * 0.5);
        if (i < 0) i = 0;
        if (i > 95) i = 95;
        while (i > 0 && (i * (193 - i)) / 2 > idx) i--;
        while (i < 95 && ((i + 1) * (192 - i)) / 2 <= idx) i++;
        int j = i + idx - (i * (193 - i)) / 2;
        float a = adj[indsh[i] * NV + indsh[j]];
        float t = g_out[idx];
        s += fmaxf(a, 0.f) - a * t + log1pf(expf(-fabsf(a)));
    }
    float w = 0.f;
    for (int o = tid; o < LAT; o += TPB) {
        float smu = bmu[o], sls = bls[o];
#pragma unroll
        for (int c = 0; c < 16; c++) { smu += g_p_mu[c][o]; sls += g_p_ls[c][o]; }
        w += 1.f + sls - smu * smu - expf(sls);
    }
    for (int off = 16; off; off >>= 1) {
        s += __shfl_down_sync(FULLW, s, off);
        w += __shfl_down_sync(FULLW, w, off);
    }
    if ((tid & 31) == 0) { red[tid >> 5] = s; redk[tid >> 5] = w; }
    __syncthreads();
    if (tid == 0) {
        float S = ((red[0] + red[1]) + (red[2] + red[3])) + (red[4] + red[5]);
        float W = ((redk[0] + redk[1]) + (redk[2] + redk[3])) + (redk[4] + redk[5]);
        out[0] = S / (float)OUTD + (-0.5f * W / (float)NNE);
    }
}

extern "C" void kernel_launch(void* const* d_in, const int* in_sizes, int n_in,
                              void* d_out, int out_size) {
    const float* h   = (const float*)d_in[0];
    const float* adj = (const float*)d_in[1];
    const float* Wmu = (const float*)d_in[2];
    const float* bmu = (const float*)d_in[3];
    const float* Wls = (const float*)d_in[4];
    const float* bls = (const float*)d_in[5];
    const float* Wd1 = (const float*)d_in[6];
    const float* bd1 = (const float*)d_in[7];
    const float* Wd2 = (const float*)d_in[8];
    const float* bd2 = (const float*)d_in[9];
    float* out = (float*)d_out;

    static int smem_set = 0;
    if (!smem_set) {
        cudaFuncSetAttribute(k_mpm, cudaFuncAttributeMaxDynamicSharedMemorySize,
                             (NV * 97 + NNE) * 4);
        cudaFuncSetAttribute(k_hung, cudaFuncAttributeMaxDynamicSharedMemorySize,
                             NNE * 4);
        smem_set = 1;
    }

    dim3 g1(16, 2);
    k_gemv1<<<g1, 256>>>(h, Wmu, Wls);
    k_gemv2<<<16, 256>>>(h, Wd1, bmu);
    k_out<<<19, 256>>>(Wd2, bd2, bd1);
    k_mpm<<<NC, TPB, (NV * 97 + NNE) * 4>>>(adj);
    k_hung<<<1, TPB, NNE * 4>>>(adj, bmu, bls, out);
}

// round 16
// speedup vs baseline: 1.0705x; 1.0240x over previous
#include <cuda_runtime.h>

#define NV 96
#define NNE 9216
#define LAT 256
#define OUTD 4656
#define ITERS 50
#define FULLW 0xffffffffu
#define KINIT 0xFFFFFFFEu
#define NC 48
#define TPB 192

__device__ float g_p_mu[16][LAT];
__device__ float g_p_ls[16][LAT];
__device__ float g_p_y[16][LAT];
__device__ float g_out[OUTD];
__device__ float g_xf[NNE];
__device__ float g_M[2][NNE];
__device__ int   g_scale[64];
__device__ unsigned g_arr[NC];     // monotonic barrier flags

// ---------------- MLP ----------------
__global__ void k_gemv1(const float* __restrict__ h, const float* __restrict__ Wmu,
                        const float* __restrict__ Wls) {
    __shared__ float sh[576];
    int c = blockIdx.x, mat = blockIdx.y, o = threadIdx.x;
    int k0 = c * 576;
    for (int kk = o; kk < 576; kk += 256) sh[kk] = h[k0 + kk];
    __syncthreads();
    const float* Wp = (mat ? Wls : Wmu) + (size_t)k0 * LAT + o;
    float acc = 0.f;
#pragma unroll 4
    for (int kk = 0; kk < 576; kk++) acc += sh[kk] * Wp[(size_t)kk * LAT];
    if (mat) g_p_ls[c][o] = acc; else g_p_mu[c][o] = acc;
}

__global__ void k_gemv2(const float* __restrict__ h, const float* __restrict__ Wd1,
                        const float* __restrict__ bmu) {
    __shared__ float sh[592];
    int c = blockIdx.x, o = threadIdx.x;
    int k0 = c * 592;
    for (int kk = o; kk < 592; kk += 256) {
        int k = k0 + kk;
        float v;
        if (k < NNE) v = h[k];
        else {
            int oo = k - NNE;
            v = bmu[oo];
#pragma unroll
            for (int cc = 0; cc < 16; cc++) v += g_p_mu[cc][oo];
        }
        sh[kk] = v;
    }
    __syncthreads();
    const float* Wp = Wd1 + (size_t)k0 * LAT + o;
    float acc = 0.f;
#pragma unroll 4
    for (int kk = 0; kk < 592; kk++) acc += sh[kk] * Wp[(size_t)kk * LAT];
    g_p_y[c][o] = acc;
}

__global__ void k_out(const float* __restrict__ Wd2, const float* __restrict__ bd2,
                      const float* __restrict__ bd1) {
    __shared__ float ys[LAT];
    int t = threadIdx.x;
    {
        float s = bd1[t];
#pragma unroll
        for (int c = 0; c < 16; c++) s += g_p_y[c][t];
        ys[t] = fmaxf(s, 0.f);
    }
    __syncthreads();
    int o = blockIdx.x * 256 + t;
    if (o < OUTD) {
        float acc = bd2[o];
#pragma unroll 4
        for (int k = 0; k < LAT; k++) acc += ys[k] * Wd2[(size_t)k * OUTD + o];
        g_out[o] = 1.f / (1.f + expf(-acc));
    }
}

// ---------------- helpers ----------------
__device__ __forceinline__ int triidx(int a, int b) {
    return a * NV - (a * (a - 1)) / 2 + (b - a);
}
__device__ __forceinline__ float rec_of(int i, int j) {
    int a = min(i, j), b = max(i, j);
    return g_out[triidx(a, b)];
}
__device__ __forceinline__ unsigned fmap(float x) {
    unsigned b = __float_as_uint(x);
    return b ^ ((unsigned)(((int)b) >> 31) | 0x80000000u);
}
__device__ __forceinline__ float funmap(unsigned k) {
    return __uint_as_float((k & 0x80000000u) ? (k ^ 0x80000000u) : ~k);
}

// ---------------- MPM persistent kernel (48 CTAs x 192 thr, bit-identical values) ----------------
__global__ void __launch_bounds__(TPB, 1) k_mpm(const float* __restrict__ adj) {
    extern __shared__ float dyn[];
    float* Bs = dyn;               // 96*97
    float* Ms = dyn + NV * 97;     // 9216
    __shared__ float sd[NV], snf[NV], sdr[NV], snfr[NV];
    __shared__ float As2[2][NV], Ds2[2][NV], xr2[2][NV];
    __shared__ float red[6];
    __shared__ unsigned sbase;

    int tid = threadIdx.x, bid = blockIdx.x;
    int hf = tid / NV;
    int col = tid - hf * NV;
    int grow = bid * 2 + hf;
    if (tid == 0) sbase = *(volatile unsigned*)&g_arr[bid];

    // ---- setup ----
    if (tid < NV) {
        float drt = 0.f, nfrt = 0.f;
        for (int i = 0; i < NV; i++) {
            float r = rec_of(i, tid);
            nfrt += r;
            if (i == tid) drt = r;
        }
        sdr[tid] = drt;
        snfr[tid] = nfrt;
        float nft = 0.f;
        const float* arow = adj + tid * NV;
        for (int j = 0; j < NV; j++) nft += arow[j];
        sd[tid] = arow[tid];
        snf[tid] = nft;
    }
    __syncthreads();
    if (tid < NV) {
        float drt = sdr[tid];
        for (int i = 0; i < NV; i++)
            Bs[i * 97 + tid] = (i == tid) ? 0.f : rec_of(i, tid) * sdr[i] * drt;
    }
    As2[hf][col] = (grow == col) ? 0.f : adj[grow * NV + col] * sd[grow] * sd[col];
    Ds2[hf][col] = sd[grow] * sdr[col] / (fabsf(snf[grow] - snfr[col]) + 1.f);
    xr2[hf][col] = 1.f / 96.f;
    if (tid == 0) g_scale[0] = __float_as_int(1.0f);
    if (tid >= 1 && tid < 64) g_scale[tid] = 0;
    __syncthreads();
    unsigned base = sbase;

    for (int it = 0; it < ITERS; it++) {
        int mb = it & 1;
        float xv = xr2[hf][col];
        float m0 = 0.f, m1 = 0.f, m2 = 0.f, m3 = 0.f;
#pragma unroll
        for (int b = 0; b < NV; b += 4) {
            m0 = fmaxf(m0, xr2[hf][b] * Bs[b * 97 + col]);
            m1 = fmaxf(m1, xr2[hf][b + 1] * Bs[(b + 1) * 97 + col]);
            m2 = fmaxf(m2, xr2[hf][b + 2] * Bs[(b + 2) * 97 + col]);
            m3 = fmaxf(m3, xr2[hf][b + 3] * Bs[(b + 3) * 97 + col]);
        }
        __stcg(&g_M[mb][grow * NV + col], fmaxf(fmaxf(m0, m1), fmaxf(m2, m3)));
        // grid barrier: low-traffic poll (48 pollers, nanosleep backoff)
        __syncthreads();
        unsigned tgt = base + (unsigned)(it + 1);
        if (tid == 0) { __threadfence(); *(volatile unsigned*)&g_arr[bid] = tgt; }
        if (tid < NC) {
            volatile unsigned* f = (volatile unsigned*)&g_arr[tid];
            int spins = 0;
            while (*f < tgt) { if (++spins > 4) __nanosleep(40); }
        }
        __threadfence();
        __syncthreads();
        {
            const float4* src = (const float4*)&g_M[mb][0];
            float4* dst = (float4*)Ms;
            for (int i4 = tid; i4 < NNE / 4; i4 += TPB) dst[i4] = __ldcg(src + i4);
        }
        __syncthreads();
        float sv = __int_as_float(*(volatile int*)&g_scale[it]);
        float inv = (sv > 0.f) ? 1.f / sv : 1.f;
        float a0 = xv * Ds2[hf][col], a1 = 0.f, a2 = 0.f, a3 = 0.f;
#pragma unroll
        for (int j = 0; j < NV; j += 4) {
            a0 += As2[hf][j] * Ms[j * NV + col];
            a1 += As2[hf][j + 1] * Ms[(j + 1) * NV + col];
            a2 += As2[hf][j + 2] * Ms[(j + 2) * NV + col];
            a3 += As2[hf][j + 3] * Ms[(j + 3) * NV + col];
        }
        float acc = ((a0 + a1) + (a2 + a3)) * inv;
        xr2[hf][col] = acc;
        float bm = acc;
        for (int off = 16; off; off >>= 1) bm = fmaxf(bm, __shfl_down_sync(FULLW, bm, off));
        if ((tid & 31) == 0) red[tid >> 5] = bm;
        __syncthreads();
        if (tid == 0) {
            float g = fmaxf(fmaxf(fmaxf(red[0], red[1]), fmaxf(red[2], red[3])),
                            fmaxf(red[4], red[5]));
            atomicMax(&g_scale[it + 1], __float_as_int(g));
        }
    }
    __syncthreads();
    g_xf[grow * NV + col] = xr2[hf][col];
    // kernel boundary provides the final sync before k_hung
}

// ---------------- Hungarian + loss (single CTA, logic byte-identical to R15) ----------------
__global__ void __launch_bounds__(TPB, 1) k_hung(const float* __restrict__ adj,
                                                 const float* __restrict__ bmu,
                                                 const float* __restrict__ bls,
                                                 float* __restrict__ out) {
    extern __shared__ float dyn[];
    float* xf = dyn;               // 9216
    __shared__ float red[6], redk[6];
    __shared__ float u_[97], vcol[97], rmin_[97];
    __shared__ int p_[97], way_[97], rowof_[97], rarg_[97], fl[NV], fl2[NV];
    __shared__ int indsh[NV];
    __shared__ int sn0;
    int tid = threadIdx.x;

    {
        const float4* src = (const float4*)&g_xf[0];
        float4* dst = (float4*)xf;
        for (int i4 = tid; i4 < NNE / 4; i4 += TPB) dst[i4] = __ldcg(src + i4);
    }
    if (tid < 97) { u_[tid] = 0.f; p_[tid] = 0; way_[tid] = 0; rowof_[tid] = 0; }
    __syncthreads();
    // Phase A: column reduction
    if (tid < NV) {
        float best = 1e30f; int bi = 1;
        for (int i2 = 0; i2 < NV; i2++) {
            float cv = -xf[i2 * NV + tid];
            if (cv < best) { best = cv; bi = i2 + 1; }
        }
        vcol[tid + 1] = best;
        rowof_[tid + 1] = bi;
    }
    __syncthreads();
    // Phase B: greedy column assignment
    if (tid == 0) {
        int cnt = 0;
        for (int j = 1; j <= NV; j++) {
            int i = rowof_[j];
            if (way_[i] == 0) { way_[i] = 1; p_[j] = i; }
        }
        for (int i = 1; i <= NV; i++) if (way_[i] == 0) fl[cnt++] = i;
        for (int i = 0; i <= NV; i++) way_[i] = 0;
        sn0 = cnt;
    }
    __syncthreads();
    // Phase B1: row reduction for free rows
    if (tid < NV) {
        int i = tid + 1;
        float best = 1e30f; int bj = 1;
        const float* crow = &xf[tid * NV];
        for (int j = 1; j <= NV; j++) {
            float cv = -crow[j - 1] - vcol[j];
            if (cv < best) { best = cv; bj = j; }
        }
        rmin_[i] = best;
        rarg_[i] = bj;
    }
    __syncthreads();
    if (tid == 0) {
        int cnt = 0;
        int n0 = sn0;
        for (int k = 0; k < n0; k++) {
            int i = fl[k];
            u_[i] = rmin_[i];
            int j = rarg_[i];
            if (p_[j] == 0) p_[j] = i;
            else fl2[cnt++] = i;
        }
        for (int k = 0; k < cnt; k++) fl[k] = fl2[k];
        sn0 = cnt;
    }
    __syncthreads();
    // Phase C: branchless absolute-dist Dijkstra (warp 0)
    if (tid < 32) {
        int lane = tid;
        const int J0 = 1 + lane, J1 = 33 + lane, J2 = 65 + lane;
        float vst0 = vcol[J0], vst1 = vcol[J1], vst2 = vcol[J2];
        int pr0 = p_[J0], pr1 = p_[J1], pr2 = p_[J2];
        float uo0 = pr0 ? u_[pr0] : 0.f;
        float uo1 = pr1 ? u_[pr1] : 0.f;
        float uo2 = pr2 ? u_[pr2] : 0.f;
        int nf = sn0;
        for (int idx = 0; idx < nf; idx++) {
            int i = fl[idx];
            if (lane == 0) p_[0] = i;
            unsigned k0 = KINIT, k1 = KINIT, k2 = KINIT;
            float su0 = 0.f, su1 = 0.f, su2 = 0.f;
            float S = 0.f;
            float ui0 = u_[i];
            int i0 = i;
            int j0 = 0;
            __syncwarp();
            while (true) {
                bool h0 = (j0 == J0), h1 = (j0 == J1), h2 = (j0 == J2);
                su0 = h0 ? S : su0; su1 = h1 ? S : su1; su2 = h2 ? S : su2;
                k0 = h0 ? ~0u : k0; k1 = h1 ? ~0u : k1; k2 = h2 ? ~0u : k2;
                bool s0 = (k0 == ~0u), s1 = (k1 == ~0u), s2 = (k2 == ~0u);
                const float* crow = &xf[(i0 - 1) * NV];
                float c0 = (-crow[J0 - 1] - ui0 - vst0) + S;
                float c1 = (-crow[J1 - 1] - ui0 - vst1) + S;
                float c2 = (-crow[J2 - 1] - ui0 - vst2) + S;
                unsigned kc0 = fmap(c0), kc1 = fmap(c1), kc2 = fmap(c2);
                bool up0 = !s0 && (kc0 < k0);
                bool up1 = !s1 && (kc1 < k1);
                bool up2 = !s2 && (kc2 < k2);
                way_[up0 ? J0 : 0] = j0;       // way_[0] = trash, never read
                way_[up1 ? J1 : 0] = j0;
                way_[up2 ? J2 : 0] = j0;
                k0 = up0 ? kc0 : k0;
                k1 = up1 ? kc1 : k1;
                k2 = up2 ? kc2 : k2;
                unsigned lb = min(k0, min(k1, k2));
                unsigned g = __reduce_min_sync(FULLW, lb);
                unsigned bb = __ballot_sync(FULLW, lb == g);
                int owner = __ffs(bb) - 1;
                int pk; float ul;
                if (k0 == g)      { pk = J0 | (pr0 << 8); ul = uo0; }
                else if (k1 == g) { pk = J1 | (pr1 << 8); ul = uo1; }
                else              { pk = J2 | (pr2 << 8); ul = uo2; }
                pk = __shfl_sync(FULLW, pk, owner);
                ui0 = __shfl_sync(FULLW, ul, owner);
                S = funmap(g);
                j0 = pk & 0xff;
                int pj = pk >> 8;
                if (pj == 0) break;
                i0 = pj;
            }
            float Sf = S;
            if (k0 == ~0u) { float d = Sf - su0; vst0 -= d; if (pr0) u_[pr0] += d; }
            if (k1 == ~0u) { float d = Sf - su1; vst1 -= d; if (pr1) u_[pr1] += d; }
            if (k2 == ~0u) { float d = Sf - su2; vst2 -= d; if (pr2) u_[pr2] += d; }
            __syncwarp();
            if (lane == 0) {
                u_[i] += Sf;
                int jj = j0;
                while (jj) { int jn = way_[jj]; p_[jj] = p_[jn]; jj = jn; }
            }
            __syncwarp();
            pr0 = p_[J0]; pr1 = p_[J1]; pr2 = p_[J2];
            uo0 = pr0 ? u_[pr0] : 0.f;
            uo1 = pr1 ? u_[pr1] : 0.f;
            uo2 = pr2 ? u_[pr2] : 0.f;
            __syncwarp();
        }
    }
    __syncthreads();
    if (tid < NV) indsh[tid] = max(p_[tid + 1] - 1, 0);
    __syncthreads();

    // ---- final loss ----
    float s = 0.f;
    for (int idx = tid; idx < OUTD; idx += TPB) {
        int i = (int)((193.0 - sqrt(193.0 * 193.0 - 8.0 * (double)idx)) * 0.5);
        if (i < 0) i = 0;
        if (i > 95) i = 95;
        while (i > 0 && (i * (193 - i)) / 2 > idx) i--;
        while (i < 95 && ((i + 1) * (192 - i)) / 2 <= idx) i++;
        int j = i + idx - (i * (193 - i)) / 2;
        float a = adj[indsh[i] * NV + indsh[j]];
        float t = g_out[idx];
        s += fmaxf(a, 0.f) - a * t + log1pf(expf(-fabsf(a)));
    }
    float w = 0.f;
    for (int o = tid; o < LAT; o += TPB) {
        float smu = bmu[o], sls = bls[o];
#pragma unroll
        for (int c = 0; c < 16; c++) { smu += g_p_mu[c][o]; sls += g_p_ls[c][o]; }
        w += 1.f + sls - smu * smu - expf(sls);
    }
    for (int off = 16; off; off >>= 1) {
        s += __shfl_down_sync(FULLW, s, off);
        w += __shfl_down_sync(FULLW, w, off);
    }
    if ((tid & 31) == 0) { red[tid >> 5] = s; redk[tid >> 5] = w; }
    __syncthreads();
    if (tid == 0) {
        float S = ((red[0] + red[1]) + (red[2] + red[3])) + (red[4] + red[5]);
        float W = ((redk[0] + redk[1]) + (redk[2] + redk[3])) + (redk[4] + redk[5]);
        out[0] = S / (float)OUTD + (-0.5f * W / (float)NNE);
    }
}

extern "C" void kernel_launch(void* const* d_in, const int* in_sizes, int n_in,
                              void* d_out, int out_size) {
    const float* h   = (const float*)d_in[0];
    const float* adj = (const float*)d_in[1];
    const float* Wmu = (const float*)d_in[2];
    const float* bmu = (const float*)d_in[3];
    const float* Wls = (const float*)d_in[4];
    const float* bls = (const float*)d_in[5];
    const float* Wd1 = (const float*)d_in[6];
    const float* bd1 = (const float*)d_in[7];
    const float* Wd2 = (const float*)d_in[8];
    const float* bd2 = (const float*)d_in[9];
    float* out = (float*)d_out;

    static int smem_set = 0;
    if (!smem_set) {
        cudaFuncSetAttribute(k_mpm, cudaFuncAttributeMaxDynamicSharedMemorySize,
                             (NV * 97 + NNE) * 4);
        cudaFuncSetAttribute(k_hung, cudaFuncAttributeMaxDynamicSharedMemorySize,
                             NNE * 4);
        smem_set = 1;
    }

    dim3 g1(16, 2);
    k_gemv1<<<g1, 256>>>(h, Wmu, Wls);
    k_gemv2<<<16, 256>>>(h, Wd1, bmu);
    k_out<<<19, 256>>>(Wd2, bd2, bd1);
    k_mpm<<<NC, TPB, (NV * 97 + NNE) * 4>>>(adj);
    k_hung<<<1, TPB, NNE * 4>>>(adj, bmu, bls, out);
}